// round 7
// baseline (speedup 1.0000x reference)
#include <cuda_runtime.h>
#include <math.h>

#define NIN 14
#define HID 128
#define LAT 64
#define CBN 512
#define MAXN 131072

#define SQRT2_F 1.41421356237f

// ---------------- device scratch (static: no allocations allowed) ----------------
__device__ unsigned long long g_zbuf[(size_t)MAXN * 32];  // z as f32x2 pairs, 33.5MB
__device__ float g_table[CBN * 16];                       // precomputed decoder outputs
__device__ float g_cbnorm[CBN];                           // sum(c*c), XLA:GPU warp-tree order
__device__ int g_hist[CBN];
__device__ unsigned long long g_commit;                   // fixed-point sum of ||q-z||^2

// ---------------- packed f32x2 helpers ----------------
static __device__ __forceinline__ unsigned long long ffma2(unsigned long long a,
                                                           unsigned long long b,
                                                           unsigned long long c) {
    unsigned long long d;
    asm("fma.rn.f32x2 %0, %1, %2, %3;" : "=l"(d) : "l"(a), "l"(b), "l"(c));
    return d;
}
static __device__ __forceinline__ unsigned long long fadd2(unsigned long long a,
                                                           unsigned long long b) {
    unsigned long long d;
    asm("add.rn.f32x2 %0, %1, %2;" : "=l"(d) : "l"(a), "l"(b));
    return d;
}
static __device__ __forceinline__ unsigned long long pack2(float lo, float hi) {
    unsigned long long r;
    asm("mov.b64 %0, {%1, %2};" : "=l"(r) : "r"(__float_as_uint(lo)), "r"(__float_as_uint(hi)));
    return r;
}
static __device__ __forceinline__ float2 unpack2(unsigned long long v) {
    unsigned int lo, hi;
    asm("mov.b64 {%0, %1}, %2;" : "=r"(lo), "=r"(hi) : "l"(v));
    float2 r;
    r.x = __uint_as_float(lo);
    r.y = __uint_as_float(hi);
    return r;
}

// reference-style GELU: 0.5 * x * (1 + erf(x / sqrt(2))); erff == libdevice __nv_erff
// which is what XLA:GPU emits for lax.erf on f32.
static __device__ __forceinline__ float gelu_ref(float v) {
    float e = erff(v / SQRT2_F);
    return (v * (e + 1.f)) * 0.5f;
}

// XLA:GPU row-reduction emulation for a 64-wide sum-of-squares:
// lane t accumulates elements {t, t+32} as fma(v[t+32],v[t+32], v[t]*v[t]),
// then butterfly tree with offsets 16,8,4,2,1 (lane-0 grouping).
// getv(d) must return element d.
#define GPU_SUMSQ64(getv, result) do {                                        \
    float _a[32];                                                             \
    _Pragma("unroll") for (int _t = 0; _t < 32; _t++) {                       \
        float _v0 = getv(_t);                                                 \
        float _v1 = getv(_t + 32);                                            \
        _a[_t] = fmaf(_v1, _v1, _v0 * _v0);                                   \
    }                                                                         \
    _Pragma("unroll") for (int _o = 16; _o >= 1; _o >>= 1)                    \
    _Pragma("unroll") for (int _t = 0; _t < 16; _t++)                         \
        if (_t < _o) _a[_t] = _a[_t] + _a[_t + _o];                           \
    result = _a[0];                                                           \
} while (0)

// ---------------- kernel 0: zero the cross-launch scratch ----------------
__global__ void k_init() {
    int t = threadIdx.x;
    if (t < CBN) g_hist[t] = 0;
    if (t == 0) g_commit = 0ULL;
}

// ---------------- kernel 1: decoder table for all 512 codes + codebook norms ----
__global__ __launch_bounds__(256) void k_dectab(
    const float* __restrict__ cb,
    const float* __restrict__ w1, const float* __restrict__ b1,
    const float* __restrict__ g1, const float* __restrict__ bt1,
    const float* __restrict__ w2, const float* __restrict__ b2)
{
    __shared__ float w1s[LAT * HID];   // 32KB
    __shared__ float w2s[HID * NIN];   // 7KB
    __shared__ float cbuf[8][LAT];     // 2KB
    __shared__ float gbuf[8][HID];     // 4KB
    int tid = threadIdx.x;
    for (int i = tid; i < LAT * HID; i += 256) w1s[i] = w1[i];
    for (int i = tid; i < HID * NIN; i += 256) w2s[i] = w2[i];
    __syncthreads();

    int lane = tid & 31, w = tid >> 5;
    int c = blockIdx.x * 8 + w;   // grid = 64 blocks -> 512 codes

    for (int d = lane; d < LAT; d += 32) cbuf[w][d] = __ldg(&cb[c * LAT + d]);
    __syncwarp();

    // codebook norm in XLA:GPU warp-tree order
    if (lane == 0) {
        float ns;
#define GETC(d) (cbuf[w][(d)])
        GPU_SUMSQ64(GETC, ns);
#undef GETC
        g_cbnorm[c] = ns;
    }

    // decoder layer 1: sequential fma chain over d, bias added AFTER
    float h[4];
#pragma unroll
    for (int u = 0; u < 4; u++) {
        int j = u * 32 + lane;
        float acc = 0.f;
        for (int d = 0; d < LAT; d++) acc = fmaf(cbuf[w][d], w1s[d * HID + j], acc);
        h[u] = acc + __ldg(&b1[j]);
    }
    // LayerNorm with two-pass variance
    float s = (h[0] + h[1]) + (h[2] + h[3]);
#pragma unroll
    for (int o = 16; o; o >>= 1) s += __shfl_xor_sync(~0u, s, o);
    float mean = s * (1.f / HID);
    float dv[4], s2 = 0.f;
#pragma unroll
    for (int u = 0; u < 4; u++) { dv[u] = h[u] - mean; float sq = dv[u] * dv[u]; s2 = s2 + sq; }
#pragma unroll
    for (int o = 16; o; o >>= 1) s2 += __shfl_xor_sync(~0u, s2, o);
    float var = s2 * (1.f / HID);
    float rstd = 1.f / sqrtf(var + 1e-5f);
#pragma unroll
    for (int u = 0; u < 4; u++) {
        int j = u * 32 + lane;
        float t = dv[u] * rstd;
        float t2 = t * __ldg(&g1[j]);
        float v = t2 + __ldg(&bt1[j]);
        gbuf[w][j] = gelu_ref(v);
    }
    __syncwarp();
    if (lane < NIN) {
        float acc = 0.f;
        for (int j = 0; j < HID; j++) acc = fmaf(gbuf[w][j], w2s[j * NIN + lane], acc);
        g_table[c * 16 + lane] = acc + __ldg(&b2[lane]);
    }
}

// ---------------- kernel 2: encoder (warp per token) -> z to scratch ----------
__global__ __launch_bounds__(256) void k_enc(
    const float* __restrict__ x,
    const float* __restrict__ w1, const float* __restrict__ b1,
    const float* __restrict__ g1, const float* __restrict__ bt1,
    const float* __restrict__ w2, const float* __restrict__ b2, int N)
{
    __shared__ float w2s[HID * LAT];            // 32KB
    __shared__ unsigned long long gbuf[8][HID]; // 8KB
    int tid = threadIdx.x;
    for (int i = tid; i < HID * LAT; i += 256) w2s[i] = w2[i];
    __syncthreads();

    int lane = tid & 31, w = tid >> 5;

    float w1r[NIN * 4];
#pragma unroll
    for (int i = 0; i < NIN; i++)
#pragma unroll
        for (int u = 0; u < 4; u++) w1r[i * 4 + u] = __ldg(&w1[i * HID + u * 32 + lane]);
    float b1v[4], g1v[4], btv[4];
#pragma unroll
    for (int u = 0; u < 4; u++) {
        int j = u * 32 + lane;
        b1v[u] = __ldg(&b1[j]);
        g1v[u] = __ldg(&g1[j]);
        btv[u] = __ldg(&bt1[j]);
    }
    unsigned long long b2p = pack2(__ldg(&b2[2 * lane]), __ldg(&b2[2 * lane + 1]));

    int gw = blockIdx.x * 8 + w;
    int nw = gridDim.x * 8;
    for (int t = gw; t < N; t += nw) {
        const float* xp = x + (size_t)t * NIN;
        float xv[NIN];
#pragma unroll
        for (int i = 0; i < NIN; i++) xv[i] = __ldg(&xp[i]);

        // layer 1: sequential fma chain (cublas k-order), bias added after
        float h[4];
#pragma unroll
        for (int u = 0; u < 4; u++) {
            float acc = 0.f;
#pragma unroll
            for (int i = 0; i < NIN; i++) acc = fmaf(xv[i], w1r[i * 4 + u], acc);
            h[u] = acc + b1v[u];
        }
        float s = (h[0] + h[1]) + (h[2] + h[3]);
#pragma unroll
        for (int o = 16; o; o >>= 1) s += __shfl_xor_sync(~0u, s, o);
        float mean = s * (1.f / HID);
        float dv[4], s2 = 0.f;
#pragma unroll
        for (int u = 0; u < 4; u++) { dv[u] = h[u] - mean; float sq = dv[u] * dv[u]; s2 = s2 + sq; }
#pragma unroll
        for (int o = 16; o; o >>= 1) s2 += __shfl_xor_sync(~0u, s2, o);
        float var = s2 * (1.f / HID);
        float rstd = 1.f / sqrtf(var + 1e-5f);
#pragma unroll
        for (int u = 0; u < 4; u++) {
            float t1 = dv[u] * rstd;
            float t2 = t1 * g1v[u];
            float v = t2 + btv[u];
            float gl = gelu_ref(v);
            unsigned long long gi = (unsigned long long)__float_as_uint(gl);
            gbuf[w][u * 32 + lane] = (gi << 32) | gi;
        }
        __syncwarp();
        // enc2: sequential packed fma chain in k-order, bias after
        unsigned long long a0 = 0ULL;
        const unsigned long long* gp = gbuf[w];
#pragma unroll
        for (int j = 0; j < HID; j++) {
            unsigned long long wj = *(const unsigned long long*)&w2s[j * LAT + 2 * lane];
            a0 = ffma2(gp[j], wj, a0);
        }
        g_zbuf[(size_t)t * 32 + lane] = fadd2(a0, b2p);
        __syncwarp();
    }
}

// ---------------- kernel 3: VQ (thread per token), codebook in smem ----------
#define GZ(d) (((d) & 1) ? __uint_as_float((unsigned int)(z2[(d) >> 1] >> 32)) \
                         : __uint_as_float((unsigned int)z2[(d) >> 1]))

__global__ __launch_bounds__(512) void k_vq(
    const float* __restrict__ cb,
    float* __restrict__ out_rec, float* __restrict__ out_idx, int N)
{
    extern __shared__ float sm[];
    float* cbs = sm;                        // 512*64 floats = 128KB
    float* cns = sm + CBN * LAT;            // 512 floats (GPU-tree-order norms)
    int* hs = (int*)(cns + CBN);            // 512 ints
    __shared__ unsigned long long csum;

    int tid = threadIdx.x;
    for (int i = tid; i < CBN * LAT; i += 512) cbs[i] = cb[i];
    if (tid < CBN) { cns[tid] = g_cbnorm[tid]; hs[tid] = 0; }
    if (tid == 0) csum = 0ULL;
    __syncthreads();

    for (int t = blockIdx.x * 512 + tid; t < N; t += gridDim.x * 512) {
        const ulonglong2* zp = (const ulonglong2*)&g_zbuf[(size_t)t * 32];
        unsigned long long z2[32];
#pragma unroll
        for (int u = 0; u < 16; u++) {
            ulonglong2 v = zp[u];
            z2[2 * u] = v.x;
            z2[2 * u + 1] = v.y;
        }
        // ---- fast screening pass: packed fma, norm trick, track top-2 margin ----
        float best = 3.4e38f, best2 = 3.4e38f;
        int bidx = 0;
#pragma unroll 2
        for (int c = 0; c < CBN; c++) {
            const ulonglong2* cp = (const ulonglong2*)(cbs + c * LAT);
            unsigned long long a0 = 0ULL, a1 = 0ULL, a2 = 0ULL, a3 = 0ULL;
#pragma unroll
            for (int u = 0; u < 8; u++) {
                ulonglong2 p = cp[2 * u];
                ulonglong2 q = cp[2 * u + 1];
                a0 = ffma2(z2[4 * u + 0], p.x, a0);
                a1 = ffma2(z2[4 * u + 1], p.y, a1);
                a2 = ffma2(z2[4 * u + 2], q.x, a2);
                a3 = ffma2(z2[4 * u + 3], q.y, a3);
            }
            float2 f = unpack2(fadd2(fadd2(a0, a1), fadd2(a2, a3)));
            float score = fmaf(-2.f, f.x + f.y, cns[c]);
            if (score < best) { best2 = best; best = score; bidx = c; }
            else if (score < best2) { best2 = score; }
        }

        // ---- ambiguous: replicate the reference's fp32 d2 and its tie-bias ----
        // d2 = fl(fl(zz - 2*dot) + cc), zz/cc in XLA:GPU warp-tree order,
        // dot as sequential k-chain. Track top-2 with first-index-wins; then if the
        // top-2 are within ~2 ulp of the score magnitude (the final-add quantization
        // window), force the LOWER index — reproducing jnp.argmin's first-index
        // tie-break on quantized-equal scores.
        if (best2 - best < 1e-4f) {
            float zz;
            GPU_SUMSQ64(GZ, zz);
            float bestr = 3.4e38f, bestr2 = 3.4e38f;
            int bir = 0, bir2 = 0;
            for (int c = 0; c < CBN; c++) {
                const float* p = cbs + c * LAT;
                float a = 0.f;
#pragma unroll
                for (int d = 0; d < LAT; d++) a = fmaf(GZ(d), p[d], a);
                float t0 = zz - 2.f * a;
                float sc = t0 + cns[c];
                if (sc < bestr) { bestr2 = bestr; bir2 = bir; bestr = sc; bir = c; }
                else if (sc < bestr2) { bestr2 = sc; bir2 = c; }
            }
            bidx = bir;
            // quantization-tie window: ~2 ulp of the score magnitude
            float win = fabsf(bestr) * 2.4e-7f;
            if (bestr2 - bestr <= win && bir2 < bir) bidx = bir2;
        }

        // exact ||q - z||^2 for commitment loss
        float d2 = 0.f;
        const float* cr = cbs + bidx * LAT;
#pragma unroll
        for (int u = 0; u < 32; u++) {
            unsigned long long zz2 = z2[u];
            float zl = __uint_as_float((unsigned int)zz2);
            float zh = __uint_as_float((unsigned int)(zz2 >> 32));
            float dl = zl - cr[2 * u];
            float dh = zh - cr[2 * u + 1];
            d2 = fmaf(dl, dl, d2);
            d2 = fmaf(dh, dh, d2);
        }
        atomicAdd(&hs[bidx], 1);
        atomicAdd(&csum, __float2ull_rn(d2 * 4194304.f));  // 2^22 fixed point
        if (out_idx) out_idx[t] = (float)bidx;
        if (out_rec) {
            float* orp = out_rec + (size_t)t * NIN;
            const float* tb = g_table + bidx * 16;
#pragma unroll
            for (int i = 0; i < NIN; i++) orp[i] = __ldg(&tb[i]);
        }
    }
    __syncthreads();
    if (tid < CBN) {
        int v = hs[tid];
        if (v) atomicAdd(&g_hist[tid], v);
    }
    if (tid == 0) atomicAdd(&g_commit, csum);
}

// ---------------- kernel 4: finalize scalars ----------------
__global__ void k_fin(float* out_commit, float* out_perp, int N) {
    __shared__ float red[512];
    int tid = threadIdx.x;
    float p = (float)g_hist[tid] / (float)N;
    red[tid] = p * logf(p + 1e-10f);
    __syncthreads();
    for (int s = 256; s; s >>= 1) {
        if (tid < s) red[tid] += red[tid + s];
        __syncthreads();
    }
    if (tid == 0) {
        if (out_perp) *out_perp = expf(-red[0]);
        if (out_commit) {
            double sum = (double)g_commit * (1.0 / 4194304.0);
            *out_commit = (float)(0.25 * sum / ((double)N * 64.0));
        }
    }
}

// ---------------- launch ----------------
extern "C" void kernel_launch(void* const* d_in, const int* in_sizes, int n_in,
                              void* d_out, int out_size) {
    (void)n_in;
    const float* x   = (const float*)d_in[0];
    const float* ew1 = (const float*)d_in[1];
    const float* eb1 = (const float*)d_in[2];
    const float* l1g = (const float*)d_in[3];
    const float* l1b = (const float*)d_in[4];
    const float* ew2 = (const float*)d_in[5];
    const float* eb2 = (const float*)d_in[6];
    const float* cbk = (const float*)d_in[7];
    const float* dw1 = (const float*)d_in[8];
    const float* db1 = (const float*)d_in[9];
    const float* l2g = (const float*)d_in[10];
    const float* l2b = (const float*)d_in[11];
    const float* dw2 = (const float*)d_in[12];
    const float* db2 = (const float*)d_in[13];

    int N = in_sizes[0] / NIN;
    if (N > MAXN) N = MAXN;

    float* out = (float*)d_out;
    long long rec_n = (long long)N * NIN;
    long long osz = (long long)out_size;
    float* out_rec    = (osz >= rec_n)             ? out : nullptr;
    float* out_idx    = (osz >= rec_n + N)         ? out + rec_n : nullptr;
    float* out_commit = (osz >= rec_n + N + 1)     ? out + rec_n + N : nullptr;
    float* out_perp   = (osz >= rec_n + N + 2)     ? out + rec_n + N + 1 : nullptr;

    k_init<<<1, 512>>>();
    k_dectab<<<CBN / 8, 256>>>(cbk, dw1, db1, l2g, l2b, dw2, db2);
    k_enc<<<512, 256>>>(x, ew1, eb1, l1g, l1b, ew2, eb2, N);

    int smem = CBN * LAT * 4 + CBN * 4 + CBN * 4;  // 135168 B
    cudaFuncSetAttribute(k_vq, cudaFuncAttributeMaxDynamicSharedMemorySize, smem);
    k_vq<<<148, 512, smem>>>(cbk, out_rec, out_idx, N);

    k_fin<<<1, 512>>>(out_commit, out_perp, N);
}

// round 8
// speedup vs baseline: 1.1736x; 1.1736x over previous
#include <cuda_runtime.h>
#include <math.h>

#define NIN 14
#define HID 128
#define LAT 64
#define CBN 512
#define MAXN 131072

#define SQRT2_F 1.41421356237f

// ---------------- device scratch (static: no allocations allowed) ----------------
__device__ unsigned long long g_zbuf[(size_t)MAXN * 32];  // z as f32x2 pairs, 33.5MB
__device__ float g_table[CBN * 16];                       // precomputed decoder outputs
__device__ float g_cbnorm[CBN];                           // sum(c*c), XLA:GPU warp-tree order
__device__ int g_hist[CBN];
__device__ unsigned long long g_commit;                   // fixed-point sum of ||q-z||^2

// ---------------- packed f32x2 helpers ----------------
static __device__ __forceinline__ unsigned long long ffma2(unsigned long long a,
                                                           unsigned long long b,
                                                           unsigned long long c) {
    unsigned long long d;
    asm("fma.rn.f32x2 %0, %1, %2, %3;" : "=l"(d) : "l"(a), "l"(b), "l"(c));
    return d;
}
static __device__ __forceinline__ unsigned long long fadd2(unsigned long long a,
                                                           unsigned long long b) {
    unsigned long long d;
    asm("add.rn.f32x2 %0, %1, %2;" : "=l"(d) : "l"(a), "l"(b));
    return d;
}
static __device__ __forceinline__ unsigned long long pack2(float lo, float hi) {
    unsigned long long r;
    asm("mov.b64 %0, {%1, %2};" : "=l"(r) : "r"(__float_as_uint(lo)), "r"(__float_as_uint(hi)));
    return r;
}
static __device__ __forceinline__ float2 unpack2(unsigned long long v) {
    unsigned int lo, hi;
    asm("mov.b64 {%0, %1}, %2;" : "=r"(lo), "=r"(hi) : "l"(v));
    float2 r;
    r.x = __uint_as_float(lo);
    r.y = __uint_as_float(hi);
    return r;
}

// reference-style GELU: 0.5 * x * (1 + erf(x / sqrt(2)))
static __device__ __forceinline__ float gelu_ref(float v) {
    float e = erff(v / SQRT2_F);
    return (v * (e + 1.f)) * 0.5f;
}

// XLA:GPU row-reduction emulation for 64-wide sum-of-squares (bit-frozen from R7).
#define GPU_SUMSQ64(getv, result) do {                                        \
    float _a[32];                                                             \
    _Pragma("unroll") for (int _t = 0; _t < 32; _t++) {                       \
        float _v0 = getv(_t);                                                 \
        float _v1 = getv(_t + 32);                                            \
        _a[_t] = fmaf(_v1, _v1, _v0 * _v0);                                   \
    }                                                                         \
    _Pragma("unroll") for (int _o = 16; _o >= 1; _o >>= 1)                    \
    _Pragma("unroll") for (int _t = 0; _t < 16; _t++)                         \
        if (_t < _o) _a[_t] = _a[_t] + _a[_t + _o];                           \
    result = _a[0];                                                           \
} while (0)

// ---------------- kernel 0: zero the cross-launch scratch ----------------
__global__ void k_init() {
    int t = threadIdx.x;
    if (t < CBN) g_hist[t] = 0;
    if (t == 0) g_commit = 0ULL;
}

// ---------------- kernel 1: decoder table (unchanged, bit-frozen) ----------
__global__ __launch_bounds__(256) void k_dectab(
    const float* __restrict__ cb,
    const float* __restrict__ w1, const float* __restrict__ b1,
    const float* __restrict__ g1, const float* __restrict__ bt1,
    const float* __restrict__ w2, const float* __restrict__ b2)
{
    __shared__ float w1s[LAT * HID];
    __shared__ float w2s[HID * NIN];
    __shared__ float cbuf[8][LAT];
    __shared__ float gbuf[8][HID];
    int tid = threadIdx.x;
    for (int i = tid; i < LAT * HID; i += 256) w1s[i] = w1[i];
    for (int i = tid; i < HID * NIN; i += 256) w2s[i] = w2[i];
    __syncthreads();

    int lane = tid & 31, w = tid >> 5;
    int c = blockIdx.x * 8 + w;

    for (int d = lane; d < LAT; d += 32) cbuf[w][d] = __ldg(&cb[c * LAT + d]);
    __syncwarp();

    if (lane == 0) {
        float ns;
#define GETC(d) (cbuf[w][(d)])
        GPU_SUMSQ64(GETC, ns);
#undef GETC
        g_cbnorm[c] = ns;
    }

    float h[4];
#pragma unroll
    for (int u = 0; u < 4; u++) {
        int j = u * 32 + lane;
        float acc = 0.f;
        for (int d = 0; d < LAT; d++) acc = fmaf(cbuf[w][d], w1s[d * HID + j], acc);
        h[u] = acc + __ldg(&b1[j]);
    }
    float s = (h[0] + h[1]) + (h[2] + h[3]);
#pragma unroll
    for (int o = 16; o; o >>= 1) s += __shfl_xor_sync(~0u, s, o);
    float mean = s * (1.f / HID);
    float dv[4], s2 = 0.f;
#pragma unroll
    for (int u = 0; u < 4; u++) { dv[u] = h[u] - mean; float sq = dv[u] * dv[u]; s2 = s2 + sq; }
#pragma unroll
    for (int o = 16; o; o >>= 1) s2 += __shfl_xor_sync(~0u, s2, o);
    float var = s2 * (1.f / HID);
    float rstd = 1.f / sqrtf(var + 1e-5f);
#pragma unroll
    for (int u = 0; u < 4; u++) {
        int j = u * 32 + lane;
        float t = dv[u] * rstd;
        float t2 = t * __ldg(&g1[j]);
        float v = t2 + __ldg(&bt1[j]);
        gbuf[w][j] = gelu_ref(v);
    }
    __syncwarp();
    if (lane < NIN) {
        float acc = 0.f;
        for (int j = 0; j < HID; j++) acc = fmaf(gbuf[w][j], w2s[j * NIN + lane], acc);
        g_table[c * 16 + lane] = acc + __ldg(&b2[lane]);
    }
}

// ---------------- kernel 2: encoder, 4 tokens per warp -----------------------
// Per-token arithmetic order is bit-identical to R7: same h chain (w1 values
// from smem instead of registers — same values, same order), same LN shuffles,
// same gelu, same enc2 packed-fma k-chain with bias added after. Only the
// SCHEDULE changed: one w2 smem read now feeds 4 tokens (4x less crossbar),
// g broadcast via register shuffle instead of smem.
__global__ __launch_bounds__(256) void k_enc(
    const float* __restrict__ x,
    const float* __restrict__ w1, const float* __restrict__ b1,
    const float* __restrict__ g1, const float* __restrict__ bt1,
    const float* __restrict__ w2, const float* __restrict__ b2, int N)
{
    __shared__ float w1s[NIN * HID];   // 7KB
    __shared__ float w2s[HID * LAT];   // 32KB
    int tid = threadIdx.x;
    for (int i = tid; i < NIN * HID; i += 256) w1s[i] = w1[i];
    for (int i = tid; i < HID * LAT; i += 256) w2s[i] = w2[i];
    __syncthreads();

    int lane = tid & 31, w = tid >> 5;

    float b1v[4], g1v[4], btv[4];
#pragma unroll
    for (int u = 0; u < 4; u++) {
        int j = u * 32 + lane;
        b1v[u] = __ldg(&b1[j]);
        g1v[u] = __ldg(&g1[j]);
        btv[u] = __ldg(&bt1[j]);
    }
    unsigned long long b2p = pack2(__ldg(&b2[2 * lane]), __ldg(&b2[2 * lane + 1]));

    int gw = blockIdx.x * 8 + w;
    int nw = gridDim.x * 8;

    for (int t0 = gw * 4; t0 < N; t0 += nw * 4) {
        // ---- front phase: enc1 + LN + GELU for 4 tokens (per-token order frozen) --
        float gl[4][4];
#pragma unroll
        for (int m = 0; m < 4; m++) {
            int t = t0 + m;
            if (t >= N) { gl[m][0] = gl[m][1] = gl[m][2] = gl[m][3] = 0.f; continue; }
            const float* xp = x + (size_t)t * NIN;
            float xv[NIN];
#pragma unroll
            for (int i = 0; i < NIN; i++) xv[i] = __ldg(&xp[i]);
            float h[4];
#pragma unroll
            for (int u = 0; u < 4; u++) {
                float acc = 0.f;
#pragma unroll
                for (int i = 0; i < NIN; i++) acc = fmaf(xv[i], w1s[i * HID + u * 32 + lane], acc);
                h[u] = acc + b1v[u];
            }
            float s = (h[0] + h[1]) + (h[2] + h[3]);
#pragma unroll
            for (int o = 16; o; o >>= 1) s += __shfl_xor_sync(~0u, s, o);
            float mean = s * (1.f / HID);
            float dv[4], s2 = 0.f;
#pragma unroll
            for (int u = 0; u < 4; u++) { dv[u] = h[u] - mean; float sq = dv[u] * dv[u]; s2 = s2 + sq; }
#pragma unroll
            for (int o = 16; o; o >>= 1) s2 += __shfl_xor_sync(~0u, s2, o);
            float var = s2 * (1.f / HID);
            float rstd = 1.f / sqrtf(var + 1e-5f);
#pragma unroll
            for (int u = 0; u < 4; u++) {
                float t1 = dv[u] * rstd;
                float t2 = t1 * g1v[u];
                float v = t2 + btv[u];
                gl[m][u] = gelu_ref(v);
            }
        }
        // ---- enc2: one w2 read serves 4 tokens; g via register shuffle ---------
        unsigned long long acc0 = 0ULL, acc1 = 0ULL, acc2 = 0ULL, acc3 = 0ULL;
#pragma unroll
        for (int u = 0; u < 4; u++) {
            float gA = gl[0][u], gB = gl[1][u], gC = gl[2][u], gD = gl[3][u];
#pragma unroll 8
            for (int jj = 0; jj < 32; jj++) {
                int j = u * 32 + jj;
                unsigned long long wj = *(const unsigned long long*)&w2s[j * LAT + 2 * lane];
                float g0 = __shfl_sync(~0u, gA, jj);
                float g1f = __shfl_sync(~0u, gB, jj);
                float g2 = __shfl_sync(~0u, gC, jj);
                float g3 = __shfl_sync(~0u, gD, jj);
                acc0 = ffma2(pack2(g0, g0), wj, acc0);
                acc1 = ffma2(pack2(g1f, g1f), wj, acc1);
                acc2 = ffma2(pack2(g2, g2), wj, acc2);
                acc3 = ffma2(pack2(g3, g3), wj, acc3);
            }
        }
        if (t0 + 0 < N) g_zbuf[(size_t)(t0 + 0) * 32 + lane] = fadd2(acc0, b2p);
        if (t0 + 1 < N) g_zbuf[(size_t)(t0 + 1) * 32 + lane] = fadd2(acc1, b2p);
        if (t0 + 2 < N) g_zbuf[(size_t)(t0 + 2) * 32 + lane] = fadd2(acc2, b2p);
        if (t0 + 3 < N) g_zbuf[(size_t)(t0 + 3) * 32 + lane] = fadd2(acc3, b2p);
    }
}

// ---------------- kernel 3: VQ, 2 tokens per thread -------------------------
#define GZ_ARR(arr, d) (((d) & 1) ? __uint_as_float((unsigned int)((arr)[(d) >> 1] >> 32)) \
                                  : __uint_as_float((unsigned int)(arr)[(d) >> 1]))
#define GZ_A(d) GZ_ARR(z2a, d)
#define GZ_B(d) GZ_ARR(z2b, d)

// Rescue (bit-frozen from R7): reference-replica d2 + quantization-tie force.
#define RESCUE(GETV, BIDXVAR) do {                                            \
    float zz_;                                                                \
    GPU_SUMSQ64(GETV, zz_);                                                   \
    float bestr_ = 3.4e38f, bestr2_ = 3.4e38f;                                \
    int bir_ = 0, bir2_ = 0;                                                  \
    for (int c_ = 0; c_ < CBN; c_++) {                                        \
        const float* p_ = cbs + c_ * LAT;                                     \
        float a_ = 0.f;                                                       \
        _Pragma("unroll") for (int d_ = 0; d_ < LAT; d_++)                    \
            a_ = fmaf(GETV(d_), p_[d_], a_);                                  \
        float t0_ = zz_ - 2.f * a_;                                           \
        float sc_ = t0_ + cns[c_];                                            \
        if (sc_ < bestr_) { bestr2_ = bestr_; bir2_ = bir_; bestr_ = sc_; bir_ = c_; } \
        else if (sc_ < bestr2_) { bestr2_ = sc_; bir2_ = c_; }                \
    }                                                                         \
    BIDXVAR = bir_;                                                           \
    float win_ = fabsf(bestr_) * 2.4e-7f;                                     \
    if (bestr2_ - bestr_ <= win_ && bir2_ < bir_) BIDXVAR = bir2_;            \
} while (0)

#define EPILOGUE(ARR, BIDX, T) do {                                           \
    float d2_ = 0.f;                                                          \
    const float* cr_ = cbs + (BIDX) * LAT;                                    \
    _Pragma("unroll") for (int u_ = 0; u_ < 32; u_++) {                       \
        unsigned long long zz2_ = (ARR)[u_];                                  \
        float zl_ = __uint_as_float((unsigned int)zz2_);                      \
        float zh_ = __uint_as_float((unsigned int)(zz2_ >> 32));              \
        float dl_ = zl_ - cr_[2 * u_];                                        \
        float dh_ = zh_ - cr_[2 * u_ + 1];                                    \
        d2_ = fmaf(dl_, dl_, d2_);                                            \
        d2_ = fmaf(dh_, dh_, d2_);                                            \
    }                                                                         \
    atomicAdd(&hs[BIDX], 1);                                                  \
    atomicAdd(&csum, __float2ull_rn(d2_ * 4194304.f));                        \
    if (out_idx) out_idx[T] = (float)(BIDX);                                  \
    if (out_rec) {                                                            \
        float* orp_ = out_rec + (size_t)(T) * NIN;                            \
        const float* tb_ = g_table + (BIDX) * 16;                             \
        _Pragma("unroll") for (int i_ = 0; i_ < NIN; i_++)                    \
            orp_[i_] = __ldg(&tb_[i_]);                                       \
    }                                                                         \
} while (0)

__global__ __launch_bounds__(256) void k_vq(
    const float* __restrict__ cb,
    float* __restrict__ out_rec, float* __restrict__ out_idx, int N)
{
    extern __shared__ float sm[];
    float* cbs = sm;                        // 512*64 floats = 128KB
    float* cns = sm + CBN * LAT;            // 512 floats
    int* hs = (int*)(cns + CBN);            // 512 ints
    __shared__ unsigned long long csum;

    int tid = threadIdx.x;
    for (int i = tid; i < CBN * LAT; i += 256) cbs[i] = cb[i];
    for (int i = tid; i < CBN; i += 256) { cns[i] = g_cbnorm[i]; hs[i] = 0; }
    if (tid == 0) csum = 0ULL;
    __syncthreads();

    for (int base = blockIdx.x * 512; base < N; base += gridDim.x * 512) {
        int ta = base + tid;
        int tb = base + 256 + tid;
        bool va = ta < N, vb = tb < N;
        int la = va ? ta : 0;
        int lb = vb ? tb : la;

        unsigned long long z2a[32], z2b[32];
        {
            const ulonglong2* zp = (const ulonglong2*)&g_zbuf[(size_t)la * 32];
#pragma unroll
            for (int u = 0; u < 16; u++) {
                ulonglong2 v = zp[u];
                z2a[2 * u] = v.x;
                z2a[2 * u + 1] = v.y;
            }
        }
        {
            const ulonglong2* zp = (const ulonglong2*)&g_zbuf[(size_t)lb * 32];
#pragma unroll
            for (int u = 0; u < 16; u++) {
                ulonglong2 v = zp[u];
                z2b[2 * u] = v.x;
                z2b[2 * u + 1] = v.y;
            }
        }

        // ---- dual-token screening: 16 broadcast LDS feed 64 ffma2 ----
        float bestA = 3.4e38f, best2A = 3.4e38f, bestB = 3.4e38f, best2B = 3.4e38f;
        int bidxA = 0, bidxB = 0;
#pragma unroll 2
        for (int c = 0; c < CBN; c++) {
            const ulonglong2* cp = (const ulonglong2*)(cbs + c * LAT);
            unsigned long long aA0 = 0ULL, aA1 = 0ULL, aA2 = 0ULL, aA3 = 0ULL;
            unsigned long long aB0 = 0ULL, aB1 = 0ULL, aB2 = 0ULL, aB3 = 0ULL;
#pragma unroll
            for (int u = 0; u < 8; u++) {
                ulonglong2 p = cp[2 * u];
                ulonglong2 q = cp[2 * u + 1];
                aA0 = ffma2(z2a[4 * u + 0], p.x, aA0);
                aA1 = ffma2(z2a[4 * u + 1], p.y, aA1);
                aA2 = ffma2(z2a[4 * u + 2], q.x, aA2);
                aA3 = ffma2(z2a[4 * u + 3], q.y, aA3);
                aB0 = ffma2(z2b[4 * u + 0], p.x, aB0);
                aB1 = ffma2(z2b[4 * u + 1], p.y, aB1);
                aB2 = ffma2(z2b[4 * u + 2], q.x, aB2);
                aB3 = ffma2(z2b[4 * u + 3], q.y, aB3);
            }
            float cn = cns[c];
            float2 fA = unpack2(fadd2(fadd2(aA0, aA1), fadd2(aA2, aA3)));
            float scoreA = fmaf(-2.f, fA.x + fA.y, cn);
            if (scoreA < bestA) { best2A = bestA; bestA = scoreA; bidxA = c; }
            else if (scoreA < best2A) { best2A = scoreA; }
            float2 fB = unpack2(fadd2(fadd2(aB0, aB1), fadd2(aB2, aB3)));
            float scoreB = fmaf(-2.f, fB.x + fB.y, cn);
            if (scoreB < bestB) { best2B = bestB; bestB = scoreB; bidxB = c; }
            else if (scoreB < best2B) { best2B = scoreB; }
        }

        if (best2A - bestA < 1e-4f) RESCUE(GZ_A, bidxA);
        if (best2B - bestB < 1e-4f) RESCUE(GZ_B, bidxB);

        if (va) EPILOGUE(z2a, bidxA, ta);
        if (vb) EPILOGUE(z2b, bidxB, tb);
    }
    __syncthreads();
    for (int i = tid; i < CBN; i += 256) {
        int v = hs[i];
        if (v) atomicAdd(&g_hist[i], v);
    }
    if (tid == 0) atomicAdd(&g_commit, csum);
}

// ---------------- kernel 4: finalize scalars ----------------
__global__ void k_fin(float* out_commit, float* out_perp, int N) {
    __shared__ float red[512];
    int tid = threadIdx.x;
    float p = (float)g_hist[tid] / (float)N;
    red[tid] = p * logf(p + 1e-10f);
    __syncthreads();
    for (int s = 256; s; s >>= 1) {
        if (tid < s) red[tid] += red[tid + s];
        __syncthreads();
    }
    if (tid == 0) {
        if (out_perp) *out_perp = expf(-red[0]);
        if (out_commit) {
            double sum = (double)g_commit * (1.0 / 4194304.0);
            *out_commit = (float)(0.25 * sum / ((double)N * 64.0));
        }
    }
}

// ---------------- launch ----------------
extern "C" void kernel_launch(void* const* d_in, const int* in_sizes, int n_in,
                              void* d_out, int out_size) {
    (void)n_in;
    const float* x   = (const float*)d_in[0];
    const float* ew1 = (const float*)d_in[1];
    const float* eb1 = (const float*)d_in[2];
    const float* l1g = (const float*)d_in[3];
    const float* l1b = (const float*)d_in[4];
    const float* ew2 = (const float*)d_in[5];
    const float* eb2 = (const float*)d_in[6];
    const float* cbk = (const float*)d_in[7];
    const float* dw1 = (const float*)d_in[8];
    const float* db1 = (const float*)d_in[9];
    const float* l2g = (const float*)d_in[10];
    const float* l2b = (const float*)d_in[11];
    const float* dw2 = (const float*)d_in[12];
    const float* db2 = (const float*)d_in[13];

    int N = in_sizes[0] / NIN;
    if (N > MAXN) N = MAXN;

    float* out = (float*)d_out;
    long long rec_n = (long long)N * NIN;
    long long osz = (long long)out_size;
    float* out_rec    = (osz >= rec_n)             ? out : nullptr;
    float* out_idx    = (osz >= rec_n + N)         ? out + rec_n : nullptr;
    float* out_commit = (osz >= rec_n + N + 1)     ? out + rec_n + N : nullptr;
    float* out_perp   = (osz >= rec_n + N + 2)     ? out + rec_n + N + 1 : nullptr;

    k_init<<<1, 512>>>();
    k_dectab<<<CBN / 8, 256>>>(cbk, dw1, db1, l2g, l2b, dw2, db2);
    k_enc<<<296, 256>>>(x, ew1, eb1, l1g, l1b, ew2, eb2, N);

    int smem = CBN * LAT * 4 + CBN * 4 + CBN * 4;  // 135168 B
    cudaFuncSetAttribute(k_vq, cudaFuncAttributeMaxDynamicSharedMemorySize, smem);
    k_vq<<<148, 256, smem>>>(cbk, out_rec, out_idx, N);

    k_fin<<<1, 512>>>(out_commit, out_perp, N);
}

// round 9
// speedup vs baseline: 1.3027x; 1.1100x over previous
#include <cuda_runtime.h>
#include <math.h>

#define NIN 14
#define HID 128
#define LAT 64
#define CBN 512
#define MAXN 131072

#define SQRT2_F 1.41421356237f

// ---------------- device scratch (static: no allocations allowed) ----------------
__device__ unsigned long long g_zbuf[(size_t)MAXN * 32];  // z as f32x2 pairs, 33.5MB
__device__ float g_table[CBN * 16];                       // precomputed decoder outputs
__device__ float g_cbnorm[CBN];                           // sum(c*c), XLA:GPU warp-tree order
__device__ int g_hist[CBN];
__device__ unsigned long long g_commit;                   // fixed-point sum of ||q-z||^2

// ---------------- packed f32x2 helpers ----------------
static __device__ __forceinline__ unsigned long long ffma2(unsigned long long a,
                                                           unsigned long long b,
                                                           unsigned long long c) {
    unsigned long long d;
    asm("fma.rn.f32x2 %0, %1, %2, %3;" : "=l"(d) : "l"(a), "l"(b), "l"(c));
    return d;
}
static __device__ __forceinline__ unsigned long long fadd2(unsigned long long a,
                                                           unsigned long long b) {
    unsigned long long d;
    asm("add.rn.f32x2 %0, %1, %2;" : "=l"(d) : "l"(a), "l"(b));
    return d;
}
static __device__ __forceinline__ unsigned long long pack2(float lo, float hi) {
    unsigned long long r;
    asm("mov.b64 %0, {%1, %2};" : "=l"(r) : "r"(__float_as_uint(lo)), "r"(__float_as_uint(hi)));
    return r;
}
static __device__ __forceinline__ float2 unpack2(unsigned long long v) {
    unsigned int lo, hi;
    asm("mov.b64 {%0, %1}, %2;" : "=r"(lo), "=r"(hi) : "l"(v));
    float2 r;
    r.x = __uint_as_float(lo);
    r.y = __uint_as_float(hi);
    return r;
}

// reference-style GELU: 0.5 * x * (1 + erf(x / sqrt(2)))
static __device__ __forceinline__ float gelu_ref(float v) {
    float e = erff(v / SQRT2_F);
    return (v * (e + 1.f)) * 0.5f;
}

// XLA:GPU row-reduction emulation for 64-wide sum-of-squares (bit-frozen from R7).
#define GPU_SUMSQ64(getv, result) do {                                        \
    float _a[32];                                                             \
    _Pragma("unroll") for (int _t = 0; _t < 32; _t++) {                       \
        float _v0 = getv(_t);                                                 \
        float _v1 = getv(_t + 32);                                            \
        _a[_t] = fmaf(_v1, _v1, _v0 * _v0);                                   \
    }                                                                         \
    _Pragma("unroll") for (int _o = 16; _o >= 1; _o >>= 1)                    \
    _Pragma("unroll") for (int _t = 0; _t < 16; _t++)                         \
        if (_t < _o) _a[_t] = _a[_t] + _a[_t + _o];                           \
    result = _a[0];                                                           \
} while (0)

// ---------------- kernel 0: zero the cross-launch scratch ----------------
__global__ void k_init() {
    int t = threadIdx.x;
    if (t < CBN) g_hist[t] = 0;
    if (t == 0) g_commit = 0ULL;
}

// ---------------- kernel 1: decoder table (unchanged, bit-frozen) ----------
__global__ __launch_bounds__(256) void k_dectab(
    const float* __restrict__ cb,
    const float* __restrict__ w1, const float* __restrict__ b1,
    const float* __restrict__ g1, const float* __restrict__ bt1,
    const float* __restrict__ w2, const float* __restrict__ b2)
{
    __shared__ float w1s[LAT * HID];
    __shared__ float w2s[HID * NIN];
    __shared__ float cbuf[8][LAT];
    __shared__ float gbuf[8][HID];
    int tid = threadIdx.x;
    for (int i = tid; i < LAT * HID; i += 256) w1s[i] = w1[i];
    for (int i = tid; i < HID * NIN; i += 256) w2s[i] = w2[i];
    __syncthreads();

    int lane = tid & 31, w = tid >> 5;
    int c = blockIdx.x * 8 + w;

    for (int d = lane; d < LAT; d += 32) cbuf[w][d] = __ldg(&cb[c * LAT + d]);
    __syncwarp();

    if (lane == 0) {
        float ns;
#define GETC(d) (cbuf[w][(d)])
        GPU_SUMSQ64(GETC, ns);
#undef GETC
        g_cbnorm[c] = ns;
    }

    float h[4];
#pragma unroll
    for (int u = 0; u < 4; u++) {
        int j = u * 32 + lane;
        float acc = 0.f;
        for (int d = 0; d < LAT; d++) acc = fmaf(cbuf[w][d], w1s[d * HID + j], acc);
        h[u] = acc + __ldg(&b1[j]);
    }
    float s = (h[0] + h[1]) + (h[2] + h[3]);
#pragma unroll
    for (int o = 16; o; o >>= 1) s += __shfl_xor_sync(~0u, s, o);
    float mean = s * (1.f / HID);
    float dv[4], s2 = 0.f;
#pragma unroll
    for (int u = 0; u < 4; u++) { dv[u] = h[u] - mean; float sq = dv[u] * dv[u]; s2 = s2 + sq; }
#pragma unroll
    for (int o = 16; o; o >>= 1) s2 += __shfl_xor_sync(~0u, s2, o);
    float var = s2 * (1.f / HID);
    float rstd = 1.f / sqrtf(var + 1e-5f);
#pragma unroll
    for (int u = 0; u < 4; u++) {
        int j = u * 32 + lane;
        float t = dv[u] * rstd;
        float t2 = t * __ldg(&g1[j]);
        float v = t2 + __ldg(&bt1[j]);
        gbuf[w][j] = gelu_ref(v);
    }
    __syncwarp();
    if (lane < NIN) {
        float acc = 0.f;
        for (int j = 0; j < HID; j++) acc = fmaf(gbuf[w][j], w2s[j * NIN + lane], acc);
        g_table[c * 16 + lane] = acc + __ldg(&b2[lane]);
    }
}

// ---------------- kernel 2: encoder, 4 tokens/warp, smem g-table enc2 --------
// Per-token arithmetic is bit-identical to R7/R8: same enc1 chain, LN shuffles,
// gelu, and enc2 j-ascending single-chain packed fma with bias after. Only the
// g-broadcast mechanism changed (smem instead of shfl) — same values/order.
__global__ __launch_bounds__(256) void k_enc(
    const float* __restrict__ x,
    const float* __restrict__ w1, const float* __restrict__ b1,
    const float* __restrict__ g1, const float* __restrict__ bt1,
    const float* __restrict__ w2, const float* __restrict__ b2, int N)
{
    extern __shared__ float esm[];
    float* w1s = esm;                                   // NIN*HID = 1792 floats
    float* w2s = w1s + NIN * HID;                       // HID*LAT = 8192 floats
    unsigned long long* gsm = (unsigned long long*)(w2s + HID * LAT);  // 8 warps*4 tok*HID ull

    int tid = threadIdx.x;
    for (int i = tid; i < NIN * HID; i += 256) w1s[i] = w1[i];
    for (int i = tid; i < HID * LAT; i += 256) w2s[i] = w2[i];
    __syncthreads();

    int lane = tid & 31, w = tid >> 5;

    float b1v[4], g1v[4], btv[4];
#pragma unroll
    for (int u = 0; u < 4; u++) {
        int j = u * 32 + lane;
        b1v[u] = __ldg(&b1[j]);
        g1v[u] = __ldg(&g1[j]);
        btv[u] = __ldg(&bt1[j]);
    }
    unsigned long long b2p = pack2(__ldg(&b2[2 * lane]), __ldg(&b2[2 * lane + 1]));

    int gw = blockIdx.x * 8 + w;
    int nw = gridDim.x * 8;

    for (int t0 = gw * 4; t0 < N; t0 += nw * 4) {
        // ---- front phase: enc1 + LN + GELU for 4 tokens (bit-frozen order) ----
        float gl[4][4];
#pragma unroll
        for (int m = 0; m < 4; m++) {
            int t = t0 + m;
            if (t >= N) { gl[m][0] = gl[m][1] = gl[m][2] = gl[m][3] = 0.f; continue; }
            const float* xp = x + (size_t)t * NIN;
            float xv[NIN];
#pragma unroll
            for (int i = 0; i < NIN; i++) xv[i] = __ldg(&xp[i]);
            float h[4];
#pragma unroll
            for (int u = 0; u < 4; u++) {
                float acc = 0.f;
#pragma unroll
                for (int i = 0; i < NIN; i++) acc = fmaf(xv[i], w1s[i * HID + u * 32 + lane], acc);
                h[u] = acc + b1v[u];
            }
            float s = (h[0] + h[1]) + (h[2] + h[3]);
#pragma unroll
            for (int o = 16; o; o >>= 1) s += __shfl_xor_sync(~0u, s, o);
            float mean = s * (1.f / HID);
            float dv[4], s2 = 0.f;
#pragma unroll
            for (int u = 0; u < 4; u++) { dv[u] = h[u] - mean; float sq = dv[u] * dv[u]; s2 = s2 + sq; }
#pragma unroll
            for (int o = 16; o; o >>= 1) s2 += __shfl_xor_sync(~0u, s2, o);
            float var = s2 * (1.f / HID);
            float rstd = 1.f / sqrtf(var + 1e-5f);
#pragma unroll
            for (int u = 0; u < 4; u++) {
                float t1 = dv[u] * rstd;
                float t2 = t1 * g1v[u];
                float v = t2 + btv[u];
                gl[m][u] = gelu_ref(v);
            }
        }
        // ---- publish g (duplicated-packed) to warp-private smem, token-major ----
#pragma unroll
        for (int m = 0; m < 4; m++)
#pragma unroll
            for (int u = 0; u < 4; u++) {
                unsigned long long gi = (unsigned long long)__float_as_uint(gl[m][u]);
                gsm[((w * 4 + m) * HID) + u * 32 + lane] = (gi << 32) | gi;
            }
        __syncwarp();
        // ---- enc2: one w2 read serves 4 tokens; g via broadcast LDS ----
        unsigned long long acc0 = 0ULL, acc1 = 0ULL, acc2 = 0ULL, acc3 = 0ULL;
        const unsigned long long* g0p = gsm + (w * 4 + 0) * HID;
        const unsigned long long* g1p = gsm + (w * 4 + 1) * HID;
        const unsigned long long* g2p = gsm + (w * 4 + 2) * HID;
        const unsigned long long* g3p = gsm + (w * 4 + 3) * HID;
#pragma unroll 8
        for (int j = 0; j < HID; j++) {
            unsigned long long wj = *(const unsigned long long*)&w2s[j * LAT + 2 * lane];
            acc0 = ffma2(g0p[j], wj, acc0);
            acc1 = ffma2(g1p[j], wj, acc1);
            acc2 = ffma2(g2p[j], wj, acc2);
            acc3 = ffma2(g3p[j], wj, acc3);
        }
        __syncwarp();
        if (t0 + 0 < N) g_zbuf[(size_t)(t0 + 0) * 32 + lane] = fadd2(acc0, b2p);
        if (t0 + 1 < N) g_zbuf[(size_t)(t0 + 1) * 32 + lane] = fadd2(acc1, b2p);
        if (t0 + 2 < N) g_zbuf[(size_t)(t0 + 2) * 32 + lane] = fadd2(acc2, b2p);
        if (t0 + 3 < N) g_zbuf[(size_t)(t0 + 3) * 32 + lane] = fadd2(acc3, b2p);
    }
}

// ---------------- kernel 3: VQ, 2 tokens/thread, software-pipelined ----------
#define GZ_ARR(arr, d) (((d) & 1) ? __uint_as_float((unsigned int)((arr)[(d) >> 1] >> 32)) \
                                  : __uint_as_float((unsigned int)(arr)[(d) >> 1]))
#define GZ_A(d) GZ_ARR(z2a, d)
#define GZ_B(d) GZ_ARR(z2b, d)

// Rescue (bit-frozen from R7): reference-replica d2 + quantization-tie force.
#define RESCUE(GETV, BIDXVAR) do {                                            \
    float zz_;                                                                \
    GPU_SUMSQ64(GETV, zz_);                                                   \
    float bestr_ = 3.4e38f, bestr2_ = 3.4e38f;                                \
    int bir_ = 0, bir2_ = 0;                                                  \
    for (int c_ = 0; c_ < CBN; c_++) {                                        \
        const float* p_ = cbs + c_ * LAT;                                     \
        float a_ = 0.f;                                                       \
        _Pragma("unroll") for (int d_ = 0; d_ < LAT; d_++)                    \
            a_ = fmaf(GETV(d_), p_[d_], a_);                                  \
        float t0_ = zz_ - 2.f * a_;                                           \
        float sc_ = t0_ + cns[c_];                                            \
        if (sc_ < bestr_) { bestr2_ = bestr_; bir2_ = bir_; bestr_ = sc_; bir_ = c_; } \
        else if (sc_ < bestr2_) { bestr2_ = sc_; bir2_ = c_; }                \
    }                                                                         \
    BIDXVAR = bir_;                                                           \
    float win_ = fabsf(bestr_) * 2.4e-7f;                                     \
    if (bestr2_ - bestr_ <= win_ && bir2_ < bir_) BIDXVAR = bir2_;            \
} while (0)

#define EPILOGUE(ARR, BIDX, T) do {                                           \
    float d2_ = 0.f;                                                          \
    const float* cr_ = cbs + (BIDX) * LAT;                                    \
    _Pragma("unroll") for (int u_ = 0; u_ < 32; u_++) {                       \
        unsigned long long zz2_ = (ARR)[u_];                                  \
        float zl_ = __uint_as_float((unsigned int)zz2_);                      \
        float zh_ = __uint_as_float((unsigned int)(zz2_ >> 32));              \
        float dl_ = zl_ - cr_[2 * u_];                                        \
        float dh_ = zh_ - cr_[2 * u_ + 1];                                    \
        d2_ = fmaf(dl_, dl_, d2_);                                            \
        d2_ = fmaf(dh_, dh_, d2_);                                            \
    }                                                                         \
    atomicAdd(&hs[BIDX], 1);                                                  \
    atomicAdd(&csum, __float2ull_rn(d2_ * 4194304.f));                        \
    if (out_idx) out_idx[T] = (float)(BIDX);                                  \
    if (out_rec) {                                                            \
        float* orp_ = out_rec + (size_t)(T) * NIN;                            \
        const float* tb_ = g_table + (BIDX) * 16;                             \
        _Pragma("unroll") for (int i_ = 0; i_ < NIN; i_++)                    \
            orp_[i_] = __ldg(&tb_[i_]);                                       \
    }                                                                         \
} while (0)

__global__ __launch_bounds__(256) void k_vq(
    const float* __restrict__ cb,
    float* __restrict__ out_rec, float* __restrict__ out_idx, int N)
{
    extern __shared__ float sm[];
    float* cbs = sm;                        // 512*64 floats = 128KB
    float* cns = sm + CBN * LAT;            // 512 floats
    int* hs = (int*)(cns + CBN);            // 512 ints
    __shared__ unsigned long long csum;

    int tid = threadIdx.x;
    for (int i = tid; i < CBN * LAT; i += 256) cbs[i] = cb[i];
    for (int i = tid; i < CBN; i += 256) { cns[i] = g_cbnorm[i]; hs[i] = 0; }
    if (tid == 0) csum = 0ULL;
    __syncthreads();

    for (int base = blockIdx.x * 512; base < N; base += gridDim.x * 512) {
        int ta = base + tid;
        int tb = base + 256 + tid;
        bool va = ta < N, vb = tb < N;
        int la = va ? ta : 0;
        int lb = vb ? tb : la;

        unsigned long long z2a[32], z2b[32];
        {
            const ulonglong2* zp = (const ulonglong2*)&g_zbuf[(size_t)la * 32];
#pragma unroll
            for (int u = 0; u < 16; u++) {
                ulonglong2 v = zp[u];
                z2a[2 * u] = v.x;
                z2a[2 * u + 1] = v.y;
            }
        }
        {
            const ulonglong2* zp = (const ulonglong2*)&g_zbuf[(size_t)lb * 32];
#pragma unroll
            for (int u = 0; u < 16; u++) {
                ulonglong2 v = zp[u];
                z2b[2 * u] = v.x;
                z2b[2 * u + 1] = v.y;
            }
        }

        // ---- screening: software-pipelined halves; LDS latency hidden by FMAs ----
        float bestA = 3.4e38f, best2A = 3.4e38f, bestB = 3.4e38f, best2B = 3.4e38f;
        int bidxA = 0, bidxB = 0;
        ulonglong2 bh0[8], bh1[8];
        {
            const ulonglong2* cp = (const ulonglong2*)cbs;
#pragma unroll
            for (int i = 0; i < 8; i++) bh0[i] = cp[i];
        }
#pragma unroll 1
        for (int c = 0; c < CBN; c++) {
            const ulonglong2* cp = (const ulonglong2*)(cbs + c * LAT);
            // prefetch second half of this code
#pragma unroll
            for (int i = 0; i < 8; i++) bh1[i] = cp[8 + i];
            unsigned long long aA0 = 0ULL, aA1 = 0ULL, aB0 = 0ULL, aB1 = 0ULL;
            // first half (dims 0..31) from bh0
#pragma unroll
            for (int u = 0; u < 4; u++) {
                aA0 = ffma2(z2a[4 * u + 0], bh0[2 * u].x, aA0);
                aA1 = ffma2(z2a[4 * u + 1], bh0[2 * u].y, aA1);
                aA0 = ffma2(z2a[4 * u + 2], bh0[2 * u + 1].x, aA0);
                aA1 = ffma2(z2a[4 * u + 3], bh0[2 * u + 1].y, aA1);
                aB0 = ffma2(z2b[4 * u + 0], bh0[2 * u].x, aB0);
                aB1 = ffma2(z2b[4 * u + 1], bh0[2 * u].y, aB1);
                aB0 = ffma2(z2b[4 * u + 2], bh0[2 * u + 1].x, aB0);
                aB1 = ffma2(z2b[4 * u + 3], bh0[2 * u + 1].y, aB1);
            }
            // prefetch first half of next code
            {
                const ulonglong2* cpn = (const ulonglong2*)(cbs + ((c + 1) & (CBN - 1)) * LAT);
#pragma unroll
                for (int i = 0; i < 8; i++) bh0[i] = cpn[i];
            }
            // second half (dims 32..63) from bh1
#pragma unroll
            for (int u = 0; u < 4; u++) {
                aA0 = ffma2(z2a[16 + 4 * u + 0], bh1[2 * u].x, aA0);
                aA1 = ffma2(z2a[16 + 4 * u + 1], bh1[2 * u].y, aA1);
                aA0 = ffma2(z2a[16 + 4 * u + 2], bh1[2 * u + 1].x, aA0);
                aA1 = ffma2(z2a[16 + 4 * u + 3], bh1[2 * u + 1].y, aA1);
                aB0 = ffma2(z2b[16 + 4 * u + 0], bh1[2 * u].x, aB0);
                aB1 = ffma2(z2b[16 + 4 * u + 1], bh1[2 * u].y, aB1);
                aB0 = ffma2(z2b[16 + 4 * u + 2], bh1[2 * u + 1].x, aB0);
                aB1 = ffma2(z2b[16 + 4 * u + 3], bh1[2 * u + 1].y, aB1);
            }
            float cn = cns[c];
            float2 fA = unpack2(fadd2(aA0, aA1));
            float scoreA = fmaf(-2.f, fA.x + fA.y, cn);
            if (scoreA < bestA) { best2A = bestA; bestA = scoreA; bidxA = c; }
            else if (scoreA < best2A) { best2A = scoreA; }
            float2 fB = unpack2(fadd2(aB0, aB1));
            float scoreB = fmaf(-2.f, fB.x + fB.y, cn);
            if (scoreB < bestB) { best2B = bestB; bestB = scoreB; bidxB = c; }
            else if (scoreB < best2B) { best2B = scoreB; }
        }

        if (best2A - bestA < 1e-4f) RESCUE(GZ_A, bidxA);
        if (best2B - bestB < 1e-4f) RESCUE(GZ_B, bidxB);

        if (va) EPILOGUE(z2a, bidxA, ta);
        if (vb) EPILOGUE(z2b, bidxB, tb);
    }
    __syncthreads();
    for (int i = tid; i < CBN; i += 256) {
        int v = hs[i];
        if (v) atomicAdd(&g_hist[i], v);
    }
    if (tid == 0) atomicAdd(&g_commit, csum);
}

// ---------------- kernel 4: finalize scalars ----------------
__global__ void k_fin(float* out_commit, float* out_perp, int N) {
    __shared__ float red[512];
    int tid = threadIdx.x;
    float p = (float)g_hist[tid] / (float)N;
    red[tid] = p * logf(p + 1e-10f);
    __syncthreads();
    for (int s = 256; s; s >>= 1) {
        if (tid < s) red[tid] += red[tid + s];
        __syncthreads();
    }
    if (tid == 0) {
        if (out_perp) *out_perp = expf(-red[0]);
        if (out_commit) {
            double sum = (double)g_commit * (1.0 / 4194304.0);
            *out_commit = (float)(0.25 * sum / ((double)N * 64.0));
        }
    }
}

// ---------------- launch ----------------
extern "C" void kernel_launch(void* const* d_in, const int* in_sizes, int n_in,
                              void* d_out, int out_size) {
    (void)n_in;
    const float* x   = (const float*)d_in[0];
    const float* ew1 = (const float*)d_in[1];
    const float* eb1 = (const float*)d_in[2];
    const float* l1g = (const float*)d_in[3];
    const float* l1b = (const float*)d_in[4];
    const float* ew2 = (const float*)d_in[5];
    const float* eb2 = (const float*)d_in[6];
    const float* cbk = (const float*)d_in[7];
    const float* dw1 = (const float*)d_in[8];
    const float* db1 = (const float*)d_in[9];
    const float* l2g = (const float*)d_in[10];
    const float* l2b = (const float*)d_in[11];
    const float* dw2 = (const float*)d_in[12];
    const float* db2 = (const float*)d_in[13];

    int N = in_sizes[0] / NIN;
    if (N > MAXN) N = MAXN;

    float* out = (float*)d_out;
    long long rec_n = (long long)N * NIN;
    long long osz = (long long)out_size;
    float* out_rec    = (osz >= rec_n)             ? out : nullptr;
    float* out_idx    = (osz >= rec_n + N)         ? out + rec_n : nullptr;
    float* out_commit = (osz >= rec_n + N + 1)     ? out + rec_n + N : nullptr;
    float* out_perp   = (osz >= rec_n + N + 2)     ? out + rec_n + N + 1 : nullptr;

    k_init<<<1, 512>>>();
    k_dectab<<<CBN / 8, 256>>>(cbk, dw1, db1, l2g, l2b, dw2, db2);

    int smem_enc = (NIN * HID + HID * LAT) * 4 + 8 * 4 * HID * 8;  // 72704 B
    cudaFuncSetAttribute(k_enc, cudaFuncAttributeMaxDynamicSharedMemorySize, smem_enc);
    k_enc<<<444, 256, smem_enc>>>(x, ew1, eb1, l1g, l1b, ew2, eb2, N);

    int smem = CBN * LAT * 4 + CBN * 4 + CBN * 4;  // 135168 B
    cudaFuncSetAttribute(k_vq, cudaFuncAttributeMaxDynamicSharedMemorySize, smem);
    k_vq<<<148, 256, smem>>>(cbk, out_rec, out_idx, N);

    k_fin<<<1, 512>>>(out_commit, out_perp, N);
}